// round 14
// baseline (speedup 1.0000x reference)
#include <cuda_runtime.h>
#include <cuda_bf16.h>
#include <cstdint>

// ============================================================================
// PTX helpers — baseline (non arch-specific) features only: ldmatrix (sm_75+),
// cp.async (sm_80+), bf16 mma.sync (sm_80+). NO tcgen05 (rejected by ptxas
// for .target sm_103 without the 'a' feature suffix).
// ============================================================================

__device__ __forceinline__ uint32_t smem_to_u32(const void* smem_ptr) {
    uint32_t addr;
    asm("{ .reg .u64 tmp; cvta.to.shared.u64 tmp, %1; cvt.u32.u64 %0, tmp; }"
        : "=r"(addr) : "l"(smem_ptr));
    return addr;
}

#define CP_ASYNC_16(smem_addr, gptr) \
    asm volatile("cp.async.cg.shared.global [%0], [%1], 16;" \
                 :: "r"((uint32_t)(smem_addr)), "l"(gptr) : "memory")

#define CP_ASYNC_COMMIT() \
    asm volatile("cp.async.commit_group;" ::: "memory")

#define CP_ASYNC_WAIT_ALL() \
    asm volatile("cp.async.wait_group 0;" ::: "memory")

#define LDSM_X4(r0, r1, r2, r3, addr) \
    asm volatile("ldmatrix.sync.aligned.m8n8.x4.shared.b16 {%0,%1,%2,%3}, [%4];" \
                 : "=r"(r0), "=r"(r1), "=r"(r2), "=r"(r3) : "r"(addr))

#define MMA_BF16(d, a0, a1, a2, a3, b0, b1) \
    asm volatile("mma.sync.aligned.m16n8k16.row.col.f32.bf16.bf16.f32 " \
                 "{%0,%1,%2,%3}, {%4,%5,%6,%7}, {%8,%9}, {%0,%1,%2,%3};" \
                 : "+f"((d)[0]), "+f"((d)[1]), "+f"((d)[2]), "+f"((d)[3]) \
                 : "r"(a0), "r"(a1), "r"(a2), "r"(a3), "r"(b0), "r"(b1))

__device__ __forceinline__ uint32_t pack2bf(float a, float b) {
    __nv_bfloat162 v = __floats2bfloat162_rn(a, b);
    return *reinterpret_cast<uint32_t*>(&v);
}

__device__ __forceinline__ uint32_t sw128(uint32_t off) {
    return off ^ ((off >> 3) & 0x70);
}

// ============================================================================
// Problem constants
// ============================================================================
static constexpr int NTOK   = 8192;   // B*S = 4*2048
static constexpr int SMALLD = 512;
static constexpr int LARGED = 1024;

// GEMM tiling: CTA = 128(M) x 256(N), K chunks of 64. 512 threads = 16 warps,
// warp grid 4x4: warp computes 32(M) x 64(N) via m16n8k16 mma.sync.
static constexpr int BM = 128;
static constexpr int BN = 256;
static constexpr int BK = 64;               // 64 bf16 = 128 B/row = SW128 atom
static constexpr int NCHUNK = SMALLD / BK;  // 8
static constexpr int THREADS = 512;

static constexpr int A_BYTES = BM * 128;    // 16 KB
static constexpr int B_BYTES = BN * 128;    // 32 KB

// Dynamic smem: [0,512) s_ids; align 1024: A0 B0 A1 B1
static constexpr int SMEM_BYTES = 1024 + 2 * (A_BYTES + B_BYTES);  // 99328

// bf16 copy of coeffs (512x512), produced once per launch.
__device__ __nv_bfloat16 g_cbf16[SMALLD * SMALLD];

// ============================================================================
// Kernel 0: coeffs fp32 -> bf16 scratch (512 KB).
// ============================================================================
__global__ __launch_bounds__(128) void convert_coeffs(
    const float* __restrict__ coeffs)
{
    int row = blockIdx.x;
    int t = threadIdx.x;
    const float4* src = reinterpret_cast<const float4*>(
        coeffs + (size_t)row * SMALLD) + t;
    float4 x = *src;
    uint2 o;
    o.x = pack2bf(x.x, x.y);
    o.y = pack2bf(x.z, x.w);
    *(reinterpret_cast<uint2*>(g_cbf16 + (size_t)row * SMALLD) + t) = o;
}

// ============================================================================
// Fused kernel:
//   out[:, 0:512]    = weight[id] + residual[id, 0:512]    (exact fp32, fused
//                      into the A-tile fill; split between the two N-CTAs)
//   out[:, 512:1024] = (gather(weight) @ coeffsT)_bf16 + residual[id, 512:]
// Double-buffered smem; per chunk: issue next B cp.async + next A LDGs,
// compute mma on current buffer, then cvt/STS next A; one __syncthreads.
// ============================================================================
__global__ __launch_bounds__(THREADS, 1) void fused_embed_kernel(
    const int* __restrict__ ids,
    const float* __restrict__ weight,
    const float* __restrict__ residual,
    float* __restrict__ out)
{
    extern __shared__ __align__(16) unsigned char dynRaw[];

    const int tid = threadIdx.x;
    const int wid = tid >> 5;
    const int lid = tid & 31;
    const int wm  = wid & 3;          // warp M index (rows wm*32..+32)
    const int wn  = wid >> 2;         // warp N index (cols wn*64..+64)
    const int n0 = blockIdx.x * BN;   // 0 or 256 (expanded-col tile)
    const int m0 = blockIdx.y * BM;   // token tile

    uint32_t raw32 = smem_to_u32(dynRaw);
    int* s_ids = reinterpret_cast<int*>(dynRaw);
    uint32_t tbase = (raw32 + 1024 + 1023u) & ~1023u;
    uint32_t aB[2] = { tbase,           tbase + A_BYTES + B_BYTES };
    uint32_t bB[2] = { tbase + A_BYTES, tbase + 2 * A_BYTES + B_BYTES };

    if (tid < BM) s_ids[tid] = ids[m0 + tid];
    __syncthreads();

    const uint32_t myHalf = blockIdx.x;  // which copy-half granules we own

    // Per-thread A-fill geometry (constant across chunks):
    //   granule g = tid + it*512 (0..1023); row r = g>>3; in-row granule cg = g&7.
    int rA[2], cgA[2], gidA[2];
    uint32_t offA[2];
    #pragma unroll
    for (int it = 0; it < 2; ++it) {
        int g = tid + it * THREADS;
        rA[it] = g >> 3;
        cgA[it] = g & 7;
        gidA[it] = s_ids[rA[it]];
        offA[it] = sw128((uint32_t)(rA[it] * 128 + cgA[it] * 16));
    }

    // Accumulators: warp tile 32x64 = 2 mtiles x 8 ntiles x 4 floats/thread.
    float acc[2][8][4];
    #pragma unroll
    for (int mt = 0; mt < 2; ++mt)
        #pragma unroll
        for (int nt = 0; nt < 8; ++nt)
            #pragma unroll
            for (int q = 0; q < 4; ++q)
                acc[mt][nt][q] = 0.0f;

    // ---- phase helpers --------------------------------------------------
    auto fill_B_async = [&](int c, int buf) {
        const int kc = c * BK;
        const uint32_t bBase = bB[buf];
        #pragma unroll
        for (int it = 0; it < 4; ++it) {
            int g = tid + it * THREADS;      // 0..2047 granules of 16B
            int r = g >> 3;                  // tile row 0..255
            int cg = g & 7;
            const __nv_bfloat16* src =
                g_cbf16 + (size_t)(n0 + r) * SMALLD + kc + cg * 8;
            CP_ASYNC_16(bBase + sw128((uint32_t)(r * 128 + cg * 16)), src);
        }
        CP_ASYNC_COMMIT();
    };

    float4 xs[2], ys[2];
    auto load_A_regs = [&](int c) {
        const int kc = c * BK;
        #pragma unroll
        for (int it = 0; it < 2; ++it) {
            const float4* src = reinterpret_cast<const float4*>(
                weight + (size_t)gidA[it] * SMALLD + kc + cgA[it] * 8);
            xs[it] = src[0];
            ys[it] = src[1];
        }
    };

    auto store_A = [&](int c, int buf) {
        const int kc = c * BK;
        const uint32_t aBase = aB[buf];
        #pragma unroll
        for (int it = 0; it < 2; ++it) {
            uint32_t v0 = pack2bf(xs[it].x, xs[it].y), v1 = pack2bf(xs[it].z, xs[it].w);
            uint32_t v2 = pack2bf(ys[it].x, ys[it].y), v3 = pack2bf(ys[it].z, ys[it].w);
            asm volatile("st.shared.v4.b32 [%0], {%1,%2,%3,%4};"
                         :: "r"(aBase + offA[it]), "r"(v0), "r"(v1), "r"(v2), "r"(v3));
        }
        // Fused exact-fp32 first-half output for this CTA's granules.
        #pragma unroll
        for (int it = 0; it < 2; ++it) {
            if ((uint32_t)(cgA[it] >> 2) == myHalf) {
                const float4* rr = reinterpret_cast<const float4*>(
                    residual + (size_t)gidA[it] * LARGED + kc + cgA[it] * 8);
                float4 ra = __ldcs(rr);
                float4 rb = __ldcs(rr + 1);
                float4 o0, o1;
                o0.x = xs[it].x + ra.x; o0.y = xs[it].y + ra.y;
                o0.z = xs[it].z + ra.z; o0.w = xs[it].w + ra.w;
                o1.x = ys[it].x + rb.x; o1.y = ys[it].y + rb.y;
                o1.z = ys[it].z + rb.z; o1.w = ys[it].w + rb.w;
                float4* oo = reinterpret_cast<float4*>(
                    out + (size_t)(m0 + rA[it]) * LARGED + kc + cgA[it] * 8);
                __stcs(oo, o0);
                __stcs(oo + 1, o1);
            }
        }
    };

    auto compute = [&](int buf) {
        const uint32_t aBase = aB[buf];
        const uint32_t bBase = bB[buf];
        #pragma unroll
        for (int ks = 0; ks < 4; ++ks) {
            // A fragments: two m16k16 tiles via ldmatrix.x4.
            // lanes 0-15 -> rows, granule 2ks; lanes 16-31 -> rows, granule 2ks+1
            // => r0..r3 = a0..a3 of mma.m16n8k16 (audited vs PTX spec).
            uint32_t a[2][4];
            #pragma unroll
            for (int mt = 0; mt < 2; ++mt) {
                int row = wm * 32 + mt * 16 + (lid & 15);
                uint32_t g = 2 * ks + (lid >> 4);
                uint32_t off = sw128((uint32_t)(row * 128 + g * 16));
                LDSM_X4(a[mt][0], a[mt][1], a[mt][2], a[mt][3], aBase + off);
            }
            // B fragments: pairs of n8k16 tiles via ldmatrix.x4.
            // lanes 0-7: (n+lr, keven) 8-15: (n+lr, kodd) 16-23: (n+8+lr, keven)
            // 24-31: (n+8+lr, kodd)  => (b0,b1) tile n, (b2,b3) tile n+8.
            #pragma unroll
            for (int np = 0; np < 4; ++np) {
                int lr = lid & 7;
                int grp = lid >> 3;
                int row = wn * 64 + np * 16 + lr + ((grp >> 1) ? 8 : 0);
                uint32_t g = 2 * ks + (grp & 1);
                uint32_t off = sw128((uint32_t)(row * 128 + g * 16));
                uint32_t b0, b1, b2, b3;
                LDSM_X4(b0, b1, b2, b3, bBase + off);
                #pragma unroll
                for (int mt = 0; mt < 2; ++mt) {
                    MMA_BF16(acc[mt][2 * np],     a[mt][0], a[mt][1], a[mt][2], a[mt][3], b0, b1);
                    MMA_BF16(acc[mt][2 * np + 1], a[mt][0], a[mt][1], a[mt][2], a[mt][3], b2, b3);
                }
            }
        }
    };

    // ---- pipelined main loop -------------------------------------------
    // Prologue: fill buffer 0.
    fill_B_async(0, 0);
    load_A_regs(0);
    store_A(0, 0);
    CP_ASYNC_WAIT_ALL();
    __syncthreads();

    for (int c = 0; c < NCHUNK; ++c) {
        const int cur = c & 1;
        if (c + 1 < NCHUNK) {
            fill_B_async(c + 1, cur ^ 1);   // async into other buffer
            load_A_regs(c + 1);             // front-batched LDG.128s (MLP=8)
        }
        compute(cur);                       // mma over current buffer
        if (c + 1 < NCHUNK) {
            store_A(c + 1, cur ^ 1);        // cvt+STS + fused fp32 copy-half
            CP_ASYNC_WAIT_ALL();
        }
        __syncthreads();                    // nxt full + cur fully consumed
    }

    // ---- epilogue: add residual, store expanded half -------------------
    // Fragment mapping: d0,d1 -> row (l>>2), cols 2(l&3),+1; d2,d3 -> row+8.
    {
        int qr = lid >> 2;                  // 0..7
        int qc = (lid & 3) * 2;             // 0,2,4,6
        #pragma unroll
        for (int mt = 0; mt < 2; ++mt) {
            int r0 = wm * 32 + mt * 16 + qr;
            int r1 = r0 + 8;
            int gid0 = s_ids[r0];
            int gid1 = s_ids[r1];
            const float* res0 = residual + (size_t)gid0 * LARGED + SMALLD + n0;
            const float* res1 = residual + (size_t)gid1 * LARGED + SMALLD + n0;
            float* out0 = out + (size_t)(m0 + r0) * LARGED + SMALLD + n0;
            float* out1 = out + (size_t)(m0 + r1) * LARGED + SMALLD + n0;
            #pragma unroll
            for (int nt = 0; nt < 8; ++nt) {
                int col = wn * 64 + nt * 8 + qc;
                float2 rv0 = __ldcs(reinterpret_cast<const float2*>(res0 + col));
                float2 rv1 = __ldcs(reinterpret_cast<const float2*>(res1 + col));
                float2 w0, w1;
                w0.x = acc[mt][nt][0] + rv0.x;
                w0.y = acc[mt][nt][1] + rv0.y;
                w1.x = acc[mt][nt][2] + rv1.x;
                w1.y = acc[mt][nt][3] + rv1.y;
                __stcs(reinterpret_cast<float2*>(out0 + col), w0);
                __stcs(reinterpret_cast<float2*>(out1 + col), w1);
            }
        }
    }
}

// ============================================================================
// kernel_launch
// Inputs (metadata order): input_ids(int32, 8192), weight(f32, 50257*512),
//   coeffs_weight(f32, 512*512), residual_weight(f32, 50257*1024)
// Output: f32, 4*2048*1024
// ============================================================================
extern "C" void kernel_launch(void* const* d_in, const int* in_sizes, int n_in,
                              void* d_out, int out_size) {
    const int*   ids = (const int*)d_in[0];
    const float* w   = (const float*)d_in[1];
    const float* cf  = (const float*)d_in[2];
    const float* res = (const float*)d_in[3];
    float* out = (float*)d_out;

    cudaFuncSetAttribute(fused_embed_kernel,
                         cudaFuncAttributeMaxDynamicSharedMemorySize, SMEM_BYTES);

    convert_coeffs<<<SMALLD, 128>>>(cf);

    dim3 grid(SMALLD / BN, NTOK / BM);  // (2, 64) = 128 CTAs, one wave
    fused_embed_kernel<<<grid, THREADS, SMEM_BYTES>>>(ids, w, res, out);
}